// round 1
// baseline (speedup 1.0000x reference)
#include <cuda_runtime.h>
#include <math.h>
#include <stdint.h>

// ---------------------------------------------------------------------------
// ConvGRU, 2 layers. 1x1 convs == token(4608) x channel GEMMs.
//   Phase A: transpose x -> token-major Xt
//   Phase B: batch GEMM: Xp[t,m,0:1024]   = Xt @ Wg0[:, :512]^T + bg0
//                        Xp[t,m,1024:1536]= Xt @ Wc0[:, :512]^T + bc0
//   Phase C: 16 sequential steps (layer 0): gates GEMM -> candidate GEMM,
//            in-place h update, store y0[t]
//   Phase D: same batch GEMMs on y0 with layer-1 weights
//   Phase E: 16 sequential steps (layer 1)
//   Phase F: out = transpose(h) + x0
// ---------------------------------------------------------------------------

#define T_STEPS 16
#define BATCH   128
#define HID     512
#define SP      36                    // H*W = 6*6
#define M_TOK   (BATCH * SP)          // 4608 tokens
#define M_ALL   (T_STEPS * M_TOK)     // 73728
#define NPROJ   1536                  // 1024 gate preacts + 512 cand preacts
#define KDIM    512

// ---- scratch (static __device__ globals; no allocation) -------------------
__device__ float g_Xt[(size_t)M_ALL * KDIM];    // 151 MB  token-major inputs
__device__ float g_Xp[(size_t)M_ALL * NPROJ];   // 453 MB  x-side preacts
__device__ float g_Y [(size_t)M_ALL * KDIM];    // 151 MB  layer-0 outputs
__device__ float g_H [(size_t)M_TOK * KDIM];    // hidden state
__device__ float g_RH[(size_t)M_TOK * KDIM];    // r * h
__device__ float g_Z [(size_t)M_TOK * KDIM];    // z gate

// ---------------------------------------------------------------------------
__global__ void zero_kern(float* __restrict__ p, int n) {
    int i = blockIdx.x * blockDim.x + threadIdx.x;
    if (i < n) p[i] = 0.0f;
}

// transpose x[b][t][c][s] -> Xt[(t*4608 + b*36 + s)*512 + c]
__global__ void transpose_x(const float* __restrict__ x, float* __restrict__ Xt) {
    int bt = blockIdx.x;                 // enumerates (b, t), t fastest
    int b = bt / T_STEPS, t = bt % T_STEPS;
    const float* src = x + (size_t)bt * (KDIM * SP);
    float* dst = Xt + ((size_t)t * M_TOK + (size_t)b * SP) * KDIM;
    __shared__ float sm[256 * 37];
    for (int ch = 0; ch < 2; ++ch) {
        __syncthreads();
        const float* s2 = src + (size_t)ch * 256 * SP;   // contiguous 9216 floats
        for (int i = threadIdx.x; i < 256 * SP; i += 256) {
            int c = i / SP, s = i - c * SP;
            sm[c * 37 + s] = s2[i];
        }
        __syncthreads();
        for (int o = threadIdx.x; o < SP * 256; o += 256) {
            int s = o >> 8, c = o & 255;                 // c fastest -> coalesced
            dst[(size_t)s * KDIM + ch * 256 + c] = sm[c * 37 + s];
        }
    }
}

// out[b][n][s] = h[(b*36+s)*512 + n] + x0[b][n][s]
__global__ void finalize_k(const float* __restrict__ H, const float* __restrict__ x0,
                           float* __restrict__ out) {
    int b = blockIdx.x;
    __shared__ float sm[SP * 261];
    for (int ch = 0; ch < 2; ++ch) {
        __syncthreads();
        for (int i = threadIdx.x; i < SP * 256; i += 256) {
            int s = i >> 8, c = i & 255;                 // coalesced read of H rows
            sm[s * 261 + c] = H[((size_t)(b * SP + s)) * KDIM + ch * 256 + c];
        }
        __syncthreads();
        for (int o = threadIdx.x; o < 256 * SP; o += 256) {
            int n = o / SP, s = o - n * SP;              // s fastest -> coalesced
            size_t oi = ((size_t)b * HID + ch * 256 + n) * SP + s;
            out[oi] = sm[s * 261 + n] + x0[oi];
        }
    }
}

// ---------------------------------------------------------------------------
// GEMM: acc[m][n] = sum_{k<512} A[m][k] * W[n][k]   (A lda=512, W row stride ldw)
// MODE 0: C[m*ldc + n] = acc + bias[n]                         (batch preacts)
// MODE 1: g = sigmoid(acc + Xp[m*1536 + n]);
//         n<512 : RH[m][n] = g*Hin[m][n];  n>=512 : Z[m][n-512] = g
// MODE 2: nn = tanh(acc + Xp[m*1536 + 1024 + n]); z=Z[m][n]; h=Hin[m][n];
//         h' = h + z*(nn - h); Hout[m][n] = h'; (Yout ? Yout[m][n] = h')
// All dims divide tile sizes exactly (M in {4608, 73728}, N in {512,1024}).
// ---------------------------------------------------------------------------
#define BM 128
#define BN 128
#define BK 16
#define SPAD 4

__device__ __forceinline__ float sigmoidf_(float x) { return 1.0f / (1.0f + expf(-x)); }

template <int MODE>
__global__ __launch_bounds__(256, 2)
void gemm512(const float* __restrict__ A,
             const float* __restrict__ W, int ldw,
             const float* __restrict__ bias,
             float* __restrict__ C, int ldc,
             const float* __restrict__ Xp,
             const float* __restrict__ Hin,
             float* __restrict__ RH,
             float* __restrict__ Zg,
             float* __restrict__ Hout,
             float* __restrict__ Yout)
{
    __shared__ float As[2][BK][BM + SPAD];
    __shared__ float Ws[2][BK][BN + SPAD];

    const int tid = threadIdx.x;
    const int m0  = blockIdx.y * BM;
    const int n0  = blockIdx.x * BN;
    const int row = tid >> 2;            // 0..63
    const int seg = tid & 3;             // 0..3
    const int tx  = tid & 15;            // n micro
    const int ty  = tid >> 4;            // m micro

    const float* Ab = A + (size_t)(m0 + row) * KDIM + seg * 4;
    const float* A2 = Ab + (size_t)64 * KDIM;
    const float* Wb = W + (size_t)(n0 + row) * ldw + seg * 4;
    const float* W2 = Wb + (size_t)64 * ldw;

    float4 pa0, pa1, pw0, pw1;

#define LOAD_TILES(KT) do {                       \
        int off_ = (KT) * BK;                     \
        pa0 = *(const float4*)(Ab + off_);        \
        pa1 = *(const float4*)(A2 + off_);        \
        pw0 = *(const float4*)(Wb + off_);        \
        pw1 = *(const float4*)(W2 + off_);        \
    } while (0)

#define STORE_TILES(BUF) do {                                            \
        int kk_ = seg * 4;                                               \
        As[BUF][kk_+0][row]    = pa0.x; As[BUF][kk_+1][row]    = pa0.y;  \
        As[BUF][kk_+2][row]    = pa0.z; As[BUF][kk_+3][row]    = pa0.w;  \
        As[BUF][kk_+0][row+64] = pa1.x; As[BUF][kk_+1][row+64] = pa1.y;  \
        As[BUF][kk_+2][row+64] = pa1.z; As[BUF][kk_+3][row+64] = pa1.w;  \
        Ws[BUF][kk_+0][row]    = pw0.x; Ws[BUF][kk_+1][row]    = pw0.y;  \
        Ws[BUF][kk_+2][row]    = pw0.z; Ws[BUF][kk_+3][row]    = pw0.w;  \
        Ws[BUF][kk_+0][row+64] = pw1.x; Ws[BUF][kk_+1][row+64] = pw1.y;  \
        Ws[BUF][kk_+2][row+64] = pw1.z; Ws[BUF][kk_+3][row+64] = pw1.w;  \
    } while (0)

    float acc[8][8];
#pragma unroll
    for (int i = 0; i < 8; ++i)
#pragma unroll
        for (int j = 0; j < 8; ++j) acc[i][j] = 0.0f;

    LOAD_TILES(0);
    STORE_TILES(0);
    __syncthreads();

    int buf = 0;
#pragma unroll 1
    for (int kt = 0; kt < KDIM / BK; ++kt) {
        if (kt < KDIM / BK - 1) LOAD_TILES(kt + 1);
#pragma unroll
        for (int k = 0; k < BK; ++k) {
            float4 a0 = *(const float4*)&As[buf][k][ty * 8];
            float4 a1 = *(const float4*)&As[buf][k][ty * 8 + 4];
            float4 w0 = *(const float4*)&Ws[buf][k][tx * 8];
            float4 w1 = *(const float4*)&Ws[buf][k][tx * 8 + 4];
            float am[8] = {a0.x, a0.y, a0.z, a0.w, a1.x, a1.y, a1.z, a1.w};
            float wn[8] = {w0.x, w0.y, w0.z, w0.w, w1.x, w1.y, w1.z, w1.w};
#pragma unroll
            for (int i = 0; i < 8; ++i)
#pragma unroll
                for (int j = 0; j < 8; ++j)
                    acc[i][j] = fmaf(am[i], wn[j], acc[i][j]);
        }
        if (kt < KDIM / BK - 1) STORE_TILES(buf ^ 1);
        __syncthreads();
        buf ^= 1;
    }

    const int nb0 = n0 + tx * 8;
#pragma unroll
    for (int i = 0; i < 8; ++i) {
        const size_t m = (size_t)(m0 + ty * 8 + i);
        if (MODE == 0) {
            float4 v0, v1;
            v0.x = acc[i][0] + bias[nb0 + 0]; v0.y = acc[i][1] + bias[nb0 + 1];
            v0.z = acc[i][2] + bias[nb0 + 2]; v0.w = acc[i][3] + bias[nb0 + 3];
            v1.x = acc[i][4] + bias[nb0 + 4]; v1.y = acc[i][5] + bias[nb0 + 5];
            v1.z = acc[i][6] + bias[nb0 + 6]; v1.w = acc[i][7] + bias[nb0 + 7];
            *(float4*)&C[m * ldc + nb0]     = v0;
            *(float4*)&C[m * ldc + nb0 + 4] = v1;
        } else if (MODE == 1) {
#pragma unroll
            for (int j = 0; j < 8; ++j) {
                int n = nb0 + j;
                float g = sigmoidf_(acc[i][j] + Xp[m * NPROJ + n]);
                if (n < 512) RH[m * KDIM + n] = g * Hin[m * KDIM + n];
                else         Zg[m * KDIM + n - 512] = g;
            }
        } else {
#pragma unroll
            for (int j = 0; j < 8; ++j) {
                int n = nb0 + j;
                float nn = tanhf(acc[i][j] + Xp[m * NPROJ + 1024 + n]);
                float z  = Zg[m * KDIM + n];
                float h  = Hin[m * KDIM + n];
                float hn = h + z * (nn - h);
                Hout[m * KDIM + n] = hn;
                if (Yout) Yout[m * KDIM + n] = hn;
            }
        }
    }
#undef LOAD_TILES
#undef STORE_TILES
}

// ---------------------------------------------------------------------------
extern "C" void kernel_launch(void* const* d_in, const int* in_sizes, int n_in,
                              void* d_out, int out_size) {
    const float* x   = (const float*)d_in[0];
    const float* x0  = (const float*)d_in[1];
    const float* Wg0 = (const float*)d_in[2];
    const float* bg0 = (const float*)d_in[3];
    const float* Wc0 = (const float*)d_in[4];
    const float* bc0 = (const float*)d_in[5];
    const float* Wg1 = (const float*)d_in[6];
    const float* bg1 = (const float*)d_in[7];
    const float* Wc1 = (const float*)d_in[8];
    const float* bc1 = (const float*)d_in[9];
    float* out = (float*)d_out;
    (void)in_sizes; (void)n_in; (void)out_size;

    float *Xt, *Xp, *Y, *H, *RH, *Z;
    cudaGetSymbolAddress((void**)&Xt, g_Xt);
    cudaGetSymbolAddress((void**)&Xp, g_Xp);
    cudaGetSymbolAddress((void**)&Y,  g_Y);
    cudaGetSymbolAddress((void**)&H,  g_H);
    cudaGetSymbolAddress((void**)&RH, g_RH);
    cudaGetSymbolAddress((void**)&Z,  g_Z);

    const size_t stepP = (size_t)M_TOK * NPROJ;   // Xp stride per timestep
    const size_t stepY = (size_t)M_TOK * KDIM;    // Y stride per timestep

    // Phase A: transpose x to token-major
    transpose_x<<<BATCH * T_STEPS, 256>>>(x, Xt);

    // Phase B: layer-0 x-side preacts (bias folded in)
    gemm512<0><<<dim3(1024 / BN, M_ALL / BM), 256>>>(Xt, Wg0, 1024, bg0, Xp, NPROJ,
                                                     nullptr, nullptr, nullptr, nullptr, nullptr, nullptr);
    gemm512<0><<<dim3(512 / BN, M_ALL / BM), 256>>>(Xt, Wc0, 1024, bc0, Xp + 1024, NPROJ,
                                                    nullptr, nullptr, nullptr, nullptr, nullptr, nullptr);

    // Phase C: layer-0 recurrence
    zero_kern<<<(M_TOK * KDIM) / 256, 256>>>(H, M_TOK * KDIM);
    for (int t = 0; t < T_STEPS; ++t) {
        const float* Xpt = Xp + (size_t)t * stepP;
        gemm512<1><<<dim3(1024 / BN, M_TOK / BM), 256>>>(H, Wg0 + 512, 1024, nullptr, nullptr, 0,
                                                         Xpt, H, RH, Z, nullptr, nullptr);
        gemm512<2><<<dim3(512 / BN, M_TOK / BM), 256>>>(RH, Wc0 + 512, 1024, nullptr, nullptr, 0,
                                                        Xpt, H, nullptr, Z, H, Y + (size_t)t * stepY);
    }

    // Phase D: layer-1 x-side preacts from y0
    gemm512<0><<<dim3(1024 / BN, M_ALL / BM), 256>>>(Y, Wg1, 1024, bg1, Xp, NPROJ,
                                                     nullptr, nullptr, nullptr, nullptr, nullptr, nullptr);
    gemm512<0><<<dim3(512 / BN, M_ALL / BM), 256>>>(Y, Wc1, 1024, bc1, Xp + 1024, NPROJ,
                                                    nullptr, nullptr, nullptr, nullptr, nullptr, nullptr);

    // Phase E: layer-1 recurrence
    zero_kern<<<(M_TOK * KDIM) / 256, 256>>>(H, M_TOK * KDIM);
    for (int t = 0; t < T_STEPS; ++t) {
        const float* Xpt = Xp + (size_t)t * stepP;
        gemm512<1><<<dim3(1024 / BN, M_TOK / BM), 256>>>(H, Wg1 + 512, 1024, nullptr, nullptr, 0,
                                                         Xpt, H, RH, Z, nullptr, nullptr);
        gemm512<2><<<dim3(512 / BN, M_TOK / BM), 256>>>(RH, Wc1 + 512, 1024, nullptr, nullptr, 0,
                                                        Xpt, H, nullptr, Z, H, nullptr);
    }

    // Phase F: out = h_last (transposed to BCHW) + x0
    finalize_k<<<BATCH, 256>>>(H, x0, out);
}

// round 4
// speedup vs baseline: 2.1422x; 2.1422x over previous
#include <cuda_runtime.h>
#include <math.h>
#include <stdint.h>

// ===========================================================================
// ConvGRU via mma.sync tf32 tensor-core GEMMs (plain sm_100 target — tcgen05
// is unavailable: harness compiles PTX at .target sm_100, not sm_100a).
//   A: transpose x -> token-major Xt
//   B: batch GEMM x-side preacts (K=512)      [MODE 0]
//   C/E: 16 sequential steps per layer: gates [MODE 1] -> candidate [MODE 2]
//   D: batch GEMM layer-1 x-side preacts from y0
//   F: out = transpose(h_last) + x0
// GEMM core: mma.sync.aligned.m16n8k8.row.col.f32.tf32.tf32.f32,
// BM=128 x BN=128 x BK=32, cp.async double-buffered smem, 8 warps (2x4),
// warp tile 64x32, fp32 accumulate.
// ===========================================================================

#define T_STEPS 16
#define BATCH   128
#define HID     512
#define SP      36
#define M_TOK   (BATCH * SP)          // 4608
#define M_ALL   (T_STEPS * M_TOK)     // 73728
#define NPROJ   1536
#define KDIM    512

#define BM 128
#define BN 128
#define BK 32
#define PAD_ROW 36                    // floats per smem row: bank = (4r+c)%32
#define STAGE_F (BM * PAD_ROW + BN * PAD_ROW)   // 9216 floats per stage
#define SMEM_FLOATS (2 * STAGE_F)               // 18432 floats = 73728 B
#define STG_PITCH 132                 // epilogue staging pitch

// ---- scratch (static __device__ globals; no allocation) -------------------
__device__ float g_Xt[(size_t)M_ALL * KDIM];
__device__ float g_Xp[(size_t)M_ALL * NPROJ];
__device__ float g_Y [(size_t)M_ALL * KDIM];
__device__ float g_H [(size_t)M_TOK * KDIM];
__device__ float g_RH[(size_t)M_TOK * KDIM];
__device__ float g_Z [(size_t)M_TOK * KDIM];

// ---------------------------------------------------------------------------
__device__ __forceinline__ uint32_t smem_u32(const void* p) {
    uint32_t a;
    asm("{ .reg .u64 t; cvta.to.shared.u64 t, %1; cvt.u32.u64 %0, t; }" : "=r"(a) : "l"(p));
    return a;
}
__device__ __forceinline__ void cp16(uint32_t dst, const void* src) {
    asm volatile("cp.async.cg.shared.global [%0], [%1], 16;" :: "r"(dst), "l"(src));
}
__device__ __forceinline__ void cp_commit() {
    asm volatile("cp.async.commit_group;" ::: "memory");
}
template <int N>
__device__ __forceinline__ void cp_wait() {
    asm volatile("cp.async.wait_group %0;" :: "n"(N) : "memory");
}
__device__ __forceinline__ void mma_tf32(float& d0, float& d1, float& d2, float& d3,
                                         uint32_t a0, uint32_t a1, uint32_t a2, uint32_t a3,
                                         uint32_t b0, uint32_t b1) {
    asm volatile(
        "mma.sync.aligned.m16n8k8.row.col.f32.tf32.tf32.f32 "
        "{%0,%1,%2,%3}, {%4,%5,%6,%7}, {%8,%9}, {%0,%1,%2,%3};"
        : "+f"(d0), "+f"(d1), "+f"(d2), "+f"(d3)
        : "r"(a0), "r"(a1), "r"(a2), "r"(a3), "r"(b0), "r"(b1));
}

// ---------------------------------------------------------------------------
__global__ void zero_kern(float* __restrict__ p, int n) {
    int i = blockIdx.x * blockDim.x + threadIdx.x;
    if (i < n) p[i] = 0.0f;
}

// transpose x[b][t][c][s] -> Xt[(t*4608 + b*36 + s)*512 + c]
__global__ void transpose_x(const float* __restrict__ x, float* __restrict__ Xt) {
    int bt = blockIdx.x;
    int b = bt / T_STEPS, t = bt % T_STEPS;
    const float* src = x + (size_t)bt * (KDIM * SP);
    float* dst = Xt + ((size_t)t * M_TOK + (size_t)b * SP) * KDIM;
    __shared__ float sm[256 * 37];
    for (int ch = 0; ch < 2; ++ch) {
        __syncthreads();
        const float* s2 = src + (size_t)ch * 256 * SP;
        for (int i = threadIdx.x; i < 256 * SP; i += 256) {
            int c = i / SP, s = i - c * SP;
            sm[c * 37 + s] = s2[i];
        }
        __syncthreads();
        for (int o = threadIdx.x; o < SP * 256; o += 256) {
            int s = o >> 8, c = o & 255;
            dst[(size_t)s * KDIM + ch * 256 + c] = sm[c * 37 + s];
        }
    }
}

// out[b][n][s] = h[(b*36+s)*512 + n] + x0[b][n][s]
__global__ void finalize_k(const float* __restrict__ H, const float* __restrict__ x0,
                           float* __restrict__ out) {
    int b = blockIdx.x;
    __shared__ float sm[SP * 261];
    for (int ch = 0; ch < 2; ++ch) {
        __syncthreads();
        for (int i = threadIdx.x; i < SP * 256; i += 256) {
            int s = i >> 8, c = i & 255;
            sm[s * 261 + c] = H[((size_t)(b * SP + s)) * KDIM + ch * 256 + c];
        }
        __syncthreads();
        for (int o = threadIdx.x; o < 256 * SP; o += 256) {
            int n = o / SP, s = o - n * SP;
            size_t oi = ((size_t)b * HID + ch * 256 + n) * SP + s;
            out[oi] = sm[s * 261 + n] + x0[oi];
        }
    }
}

// ---------------------------------------------------------------------------
// GEMM: D[m][n] = sum_{k<512} A[m][k] * W[n][k + kw0]   (tf32 mma, fp32 acc)
// MODE 0: C[m*ldc + n] = D + bias[n]
// MODE 1: g = sigmoid(D + Xp[m*1536 + n]); n<512 -> RH = g*Hin; else Z = g
// MODE 2: nn = tanh(D + Xp[m*1536 + 1024 + n]); h' = h + z*(nn - h) -> Hout, Yout
// ---------------------------------------------------------------------------
template <int MODE>
__global__ __launch_bounds__(256)
void gemm_mma(const float* __restrict__ A,
              const float* __restrict__ W, int ldw, int kw0,
              const float* __restrict__ bias,
              float* __restrict__ C, int ldc,
              const float* __restrict__ Xp,
              const float* __restrict__ Hin,
              float* __restrict__ RH,
              float* __restrict__ Zg,
              float* __restrict__ Hout,
              float* __restrict__ Yout)
{
    extern __shared__ float sm[];
    const uint32_t sb = smem_u32(sm);
    const int tid  = threadIdx.x;
    const int w    = tid >> 5;
    const int lane = tid & 31;
    const int g    = lane >> 2;       // group 0..7
    const int tig  = lane & 3;        // thread-in-group 0..3
    const int wm   = w >> 2;          // 0..1  (M: 2 x 64)
    const int wn   = w & 3;           // 0..3  (N: 4 x 32)
    const int m0   = blockIdx.y * BM;
    const int n0   = blockIdx.x * BN;

    // loader indices: 1024 16B-chunks per operand per stage, 4 per thread
    const int lr = tid >> 3;          // base row/8-chunk split handled per i
    const int lq = tid & 7;
    (void)lr; (void)lq;

    float acc[4][4][4];
#pragma unroll
    for (int mt = 0; mt < 4; ++mt)
#pragma unroll
        for (int nt = 0; nt < 4; ++nt)
#pragma unroll
            for (int c = 0; c < 4; ++c) acc[mt][nt][c] = 0.0f;

#define LOAD_STAGE(KT, S) do {                                                   \
        const int kb_ = (KT) * BK;                                               \
        const uint32_t as_ = sb + (uint32_t)((S) * STAGE_F) * 4u;                \
        const uint32_t bs_ = as_ + (uint32_t)(BM * PAD_ROW) * 4u;                \
        _Pragma("unroll")                                                        \
        for (int i = 0; i < 4; ++i) {                                            \
            int idx = tid + 256 * i;                                             \
            int r = idx >> 3, q = idx & 7;                                       \
            cp16(as_ + (uint32_t)(r * PAD_ROW) * 4u + (uint32_t)q * 16u,         \
                 A + (size_t)(m0 + r) * KDIM + kb_ + q * 4);                     \
        }                                                                        \
        _Pragma("unroll")                                                        \
        for (int i = 0; i < 4; ++i) {                                            \
            int idx = tid + 256 * i;                                             \
            int r = idx >> 3, q = idx & 7;                                       \
            cp16(bs_ + (uint32_t)(r * PAD_ROW) * 4u + (uint32_t)q * 16u,         \
                 W + (size_t)(n0 + r) * ldw + kw0 + kb_ + q * 4);                \
        }                                                                        \
        cp_commit();                                                             \
    } while (0)

    LOAD_STAGE(0, 0);

#pragma unroll 1
    for (int kt = 0; kt < KDIM / BK; ++kt) {
        if (kt + 1 < KDIM / BK) {
            LOAD_STAGE(kt + 1, (kt + 1) & 1);
            cp_wait<1>();
        } else {
            cp_wait<0>();
        }
        __syncthreads();

        const float* As = sm + (kt & 1) * STAGE_F;
        const float* Bs = As + BM * PAD_ROW;

#pragma unroll
        for (int ks = 0; ks < 4; ++ks) {
            const int k0 = ks * 8;
            uint32_t a[4][4];
#pragma unroll
            for (int mt = 0; mt < 4; ++mt) {
                const float* ap = As + (wm * 64 + mt * 16 + g) * PAD_ROW + k0 + tig;
                a[mt][0] = __float_as_uint(ap[0]);
                a[mt][1] = __float_as_uint(ap[8 * PAD_ROW]);
                a[mt][2] = __float_as_uint(ap[4]);
                a[mt][3] = __float_as_uint(ap[8 * PAD_ROW + 4]);
            }
            uint32_t b[4][2];
#pragma unroll
            for (int nt = 0; nt < 4; ++nt) {
                const float* bp = Bs + (wn * 32 + nt * 8 + g) * PAD_ROW + k0 + tig;
                b[nt][0] = __float_as_uint(bp[0]);
                b[nt][1] = __float_as_uint(bp[4]);
            }
#pragma unroll
            for (int mt = 0; mt < 4; ++mt)
#pragma unroll
                for (int nt = 0; nt < 4; ++nt)
                    mma_tf32(acc[mt][nt][0], acc[mt][nt][1], acc[mt][nt][2], acc[mt][nt][3],
                             a[mt][0], a[mt][1], a[mt][2], a[mt][3],
                             b[nt][0], b[nt][1]);
        }
        __syncthreads();   // protect buffer (kt&1) from the load issued next iter
    }

    // ---- epilogue: accs -> smem staging (pitch 132), then coalesced sweep ----
    float* stg = sm;       // 128*132 = 16896 floats <= 18432
#pragma unroll
    for (int mt = 0; mt < 4; ++mt) {
#pragma unroll
        for (int nt = 0; nt < 4; ++nt) {
            const int m = wm * 64 + mt * 16 + g;
            const int n = wn * 32 + nt * 8 + tig * 2;
            stg[m * STG_PITCH + n]           = acc[mt][nt][0];
            stg[m * STG_PITCH + n + 1]       = acc[mt][nt][1];
            stg[(m + 8) * STG_PITCH + n]     = acc[mt][nt][2];
            stg[(m + 8) * STG_PITCH + n + 1] = acc[mt][nt][3];
        }
    }
    __syncthreads();

    for (int e = tid; e < BM * BN; e += 256) {
        const int mm = e >> 7;
        const int nn = e & 127;
        const size_t m = (size_t)(m0 + mm);
        const int n = n0 + nn;
        const float d = stg[mm * STG_PITCH + nn];
        if (MODE == 0) {
            C[m * ldc + n] = d + bias[n];
        } else if (MODE == 1) {
            float gg = 1.0f / (1.0f + expf(-(d + Xp[m * NPROJ + n])));
            if (n < 512) RH[m * KDIM + n] = gg * Hin[m * KDIM + n];
            else         Zg[m * KDIM + n - 512] = gg;
        } else {
            float cn = tanhf(d + Xp[m * NPROJ + 1024 + n]);
            float z  = Zg[m * KDIM + n];
            float h  = Hin[m * KDIM + n];
            float hn = h + z * (cn - h);
            Hout[m * KDIM + n] = hn;
            if (Yout) Yout[m * KDIM + n] = hn;
        }
    }
#undef LOAD_STAGE
}

// ---------------------------------------------------------------------------
extern "C" void kernel_launch(void* const* d_in, const int* in_sizes, int n_in,
                              void* d_out, int out_size) {
    const float* x   = (const float*)d_in[0];
    const float* x0  = (const float*)d_in[1];
    const float* Wg0 = (const float*)d_in[2];
    const float* bg0 = (const float*)d_in[3];
    const float* Wc0 = (const float*)d_in[4];
    const float* bc0 = (const float*)d_in[5];
    const float* Wg1 = (const float*)d_in[6];
    const float* bg1 = (const float*)d_in[7];
    const float* Wc1 = (const float*)d_in[8];
    const float* bc1 = (const float*)d_in[9];
    float* out = (float*)d_out;
    (void)in_sizes; (void)n_in; (void)out_size;

    float *Xt, *Xp, *Y, *H, *RH, *Z;
    cudaGetSymbolAddress((void**)&Xt, g_Xt);
    cudaGetSymbolAddress((void**)&Xp, g_Xp);
    cudaGetSymbolAddress((void**)&Y,  g_Y);
    cudaGetSymbolAddress((void**)&H,  g_H);
    cudaGetSymbolAddress((void**)&RH, g_RH);
    cudaGetSymbolAddress((void**)&Z,  g_Z);

    const int SMEM_BYTES = SMEM_FLOATS * 4;   // 73728
    cudaFuncSetAttribute(gemm_mma<0>, cudaFuncAttributeMaxDynamicSharedMemorySize, SMEM_BYTES);
    cudaFuncSetAttribute(gemm_mma<1>, cudaFuncAttributeMaxDynamicSharedMemorySize, SMEM_BYTES);
    cudaFuncSetAttribute(gemm_mma<2>, cudaFuncAttributeMaxDynamicSharedMemorySize, SMEM_BYTES);

    const size_t stepP = (size_t)M_TOK * NPROJ;
    const size_t stepY = (size_t)M_TOK * KDIM;

    transpose_x<<<BATCH * T_STEPS, 256>>>(x, Xt);

    // layer-0 x-side preacts
    gemm_mma<0><<<dim3(1024 / BN, M_ALL / BM), 256, SMEM_BYTES>>>(
        Xt, Wg0, 1024, 0, bg0, Xp, NPROJ, nullptr, nullptr, nullptr, nullptr, nullptr, nullptr);
    gemm_mma<0><<<dim3(512 / BN, M_ALL / BM), 256, SMEM_BYTES>>>(
        Xt, Wc0, 1024, 0, bc0, Xp + 1024, NPROJ, nullptr, nullptr, nullptr, nullptr, nullptr, nullptr);

    // layer-0 recurrence
    zero_kern<<<(M_TOK * KDIM) / 256, 256>>>(H, M_TOK * KDIM);
    for (int t = 0; t < T_STEPS; ++t) {
        const float* Xpt = Xp + (size_t)t * stepP;
        gemm_mma<1><<<dim3(1024 / BN, M_TOK / BM), 256, SMEM_BYTES>>>(
            H, Wg0, 1024, 512, nullptr, nullptr, 0, Xpt, H, RH, Z, nullptr, nullptr);
        gemm_mma<2><<<dim3(512 / BN, M_TOK / BM), 256, SMEM_BYTES>>>(
            RH, Wc0, 1024, 512, nullptr, nullptr, 0, Xpt, H, nullptr, Z, H, Y + (size_t)t * stepY);
    }

    // layer-1 x-side preacts
    gemm_mma<0><<<dim3(1024 / BN, M_ALL / BM), 256, SMEM_BYTES>>>(
        Y, Wg1, 1024, 0, bg1, Xp, NPROJ, nullptr, nullptr, nullptr, nullptr, nullptr, nullptr);
    gemm_mma<0><<<dim3(512 / BN, M_ALL / BM), 256, SMEM_BYTES>>>(
        Y, Wc1, 1024, 0, bc1, Xp + 1024, NPROJ, nullptr, nullptr, nullptr, nullptr, nullptr, nullptr);

    // layer-1 recurrence
    zero_kern<<<(M_TOK * KDIM) / 256, 256>>>(H, M_TOK * KDIM);
    for (int t = 0; t < T_STEPS; ++t) {
        const float* Xpt = Xp + (size_t)t * stepP;
        gemm_mma<1><<<dim3(1024 / BN, M_TOK / BM), 256, SMEM_BYTES>>>(
            H, Wg1, 1024, 512, nullptr, nullptr, 0, Xpt, H, RH, Z, nullptr, nullptr);
        gemm_mma<2><<<dim3(512 / BN, M_TOK / BM), 256, SMEM_BYTES>>>(
            RH, Wc1, 1024, 512, nullptr, nullptr, 0, Xpt, H, nullptr, Z, H, nullptr);
    }

    finalize_k<<<BATCH, 256>>>(H, x0, out);
}

// round 7
// speedup vs baseline: 2.2878x; 1.0680x over previous
#include <cuda_runtime.h>
#include <math.h>
#include <stdint.h>

// ===========================================================================
// ConvGRU, mma.sync tf32 tensor cores (plain sm_100 target; tcgen05 unavailable).
// R7 = R6 resubmitted verbatim after broker-level container failure (infra;
// same error signature as R0/R2, no kernel output produced).
//
//   A: transpose x -> token-major Xt
//   B: batch GEMM layer-0 x-side preacts Xp (K=512)            [MODE 0]
//   slots s=0..16:  gates [MODE 1] -> candidate [MODE 2], dual-z:
//        z=0: L0 step t=s   (K=512, Xp precomputed)
//        z=1: L1 step t=s-1 (K=1024, A = [Y_t | h1] / [Y_t | r*h1])
//   F: out = transpose(h1_last) + x0
// ===========================================================================

#define T_STEPS 16
#define BATCH   128
#define HID     512
#define SP      36
#define M_TOK   (BATCH * SP)          // 4608
#define M_ALL   (T_STEPS * M_TOK)     // 73728
#define NPROJ   1536

#define BM 128
#define BN 128
#define BK 32
#define PROW 36                       // smem row pitch (floats)
#define NSTG 3
#define STAGE_F ((BM + BN) * PROW)    // 9216 floats / stage
#define SMEM_BYTES (NSTG * STAGE_F * 4)   // 110592 B
#define STGP 132                      // epilogue staging pitch

// ---- scratch (static __device__ globals; no allocation) -------------------
__device__ float g_Xt [(size_t)M_ALL * 512];
__device__ float g_Xp [(size_t)M_ALL * NPROJ];
__device__ float g_H0 [(size_t)M_TOK * 512];
__device__ float g_RH0[(size_t)M_TOK * 512];
__device__ float g_Z0 [(size_t)M_TOK * 512];
__device__ float g_Z1 [(size_t)M_TOK * 512];
__device__ float g_cat [(size_t)2 * M_TOK * 1024];   // two parities of [Y_t | h1]
__device__ float g_rcat[(size_t)2 * M_TOK * 1024];   // two parities of [Y_t | r*h1]

// ---------------------------------------------------------------------------
struct GP {
    const float* A;  int lda;           // A is M x lda; K = 32*nk
    const float* W;  int ldw; int kw0;
    int nk;                             // K / 32
    const float* bias;
    float* C; int ldc;                  // MODE 0
    const float* Xp;                    // MODE 1/2 (L0); null -> use bias
    const float* Hin; int ldh;
    float* RH;                          // MODE 1 out (stride ldh)
    float* Zg;                          // MODE 1 out / MODE 2 in (stride 512)
    float* D1; int ld1;                 // MODE 2 dests (null-guarded D2/D3)
    float* D2; int ld2;
    float* D3; int ld3;
};

__device__ __forceinline__ uint32_t smem_u32(const void* p) {
    uint32_t a;
    asm("{ .reg .u64 t; cvta.to.shared.u64 t, %1; cvt.u32.u64 %0, t; }" : "=r"(a) : "l"(p));
    return a;
}
__device__ __forceinline__ void cp16(uint32_t dst, const void* src) {
    asm volatile("cp.async.cg.shared.global [%0], [%1], 16;" :: "r"(dst), "l"(src));
}
__device__ __forceinline__ void cp_commit() {
    asm volatile("cp.async.commit_group;" ::: "memory");
}
template <int N>
__device__ __forceinline__ void cp_wait() {
    asm volatile("cp.async.wait_group %0;" :: "n"(N) : "memory");
}
__device__ __forceinline__ void mma_tf32(float& d0, float& d1, float& d2, float& d3,
                                         uint32_t a0, uint32_t a1, uint32_t a2, uint32_t a3,
                                         uint32_t b0, uint32_t b1) {
    asm volatile(
        "mma.sync.aligned.m16n8k8.row.col.f32.tf32.tf32.f32 "
        "{%0,%1,%2,%3}, {%4,%5,%6,%7}, {%8,%9}, {%0,%1,%2,%3};"
        : "+f"(d0), "+f"(d1), "+f"(d2), "+f"(d3)
        : "r"(a0), "r"(a1), "r"(a2), "r"(a3), "r"(b0), "r"(b1));
}

// ---------------------------------------------------------------------------
__global__ void zero_kern(float* __restrict__ p, int n) {
    int i = blockIdx.x * blockDim.x + threadIdx.x;
    if (i < n) p[i] = 0.0f;
}

// transpose x[b][t][c][s] -> Xt[(t*4608 + b*36 + s)*512 + c]
__global__ void transpose_x(const float* __restrict__ x, float* __restrict__ Xt) {
    int bt = blockIdx.x;
    int b = bt / T_STEPS, t = bt % T_STEPS;
    const float* src = x + (size_t)bt * (512 * SP);
    float* dst = Xt + ((size_t)t * M_TOK + (size_t)b * SP) * 512;
    __shared__ float sm[256 * 37];
    for (int ch = 0; ch < 2; ++ch) {
        __syncthreads();
        const float* s2 = src + (size_t)ch * 256 * SP;
        for (int i = threadIdx.x; i < 256 * SP; i += 256) {
            int c = i / SP, s = i - c * SP;
            sm[c * 37 + s] = s2[i];
        }
        __syncthreads();
        for (int o = threadIdx.x; o < SP * 256; o += 256) {
            int s = o >> 8, c = o & 255;
            dst[(size_t)s * 512 + ch * 256 + c] = sm[c * 37 + s];
        }
    }
}

// out[b][n][s] = h1[(b*36+s)*ldh + n] + x0[b][n][s]
__global__ void finalize_k(const float* __restrict__ H, int ldh,
                           const float* __restrict__ x0, float* __restrict__ out) {
    int b = blockIdx.x;
    __shared__ float sm[SP * 261];
    for (int ch = 0; ch < 2; ++ch) {
        __syncthreads();
        for (int i = threadIdx.x; i < SP * 256; i += 256) {
            int s = i >> 8, c = i & 255;
            sm[s * 261 + c] = H[(size_t)(b * SP + s) * ldh + ch * 256 + c];
        }
        __syncthreads();
        for (int o = threadIdx.x; o < 256 * SP; o += 256) {
            int n = o / SP, s = o - n * SP;
            size_t oi = ((size_t)b * HID + ch * 256 + n) * SP + s;
            out[oi] = sm[s * 261 + n] + x0[oi];
        }
    }
}

// ---------------------------------------------------------------------------
// GEMM: D[m][n] = sum_{k<32*nk} A[m][k] * W[n][kw0 + k]   (tf32 mma, fp32 acc)
// MODE 0: C[m*ldc+n] = D + bias[n]
// MODE 1: g = sigmoid(D + (Xp ? Xp[m*1536+n] : bias[n]));
//         n<512: RH[m*ldh+n] = g*Hin[m*ldh+n];  else Zg[m*512+n-512] = g
// MODE 2: nn = tanh(D + (Xp ? Xp[m*1536+1024+n] : bias[n]));
//         h' = h + z*(nn-h) -> D1 (+D2,+D3)
// Dual-z: blockIdx.z selects p0/p1.
// ---------------------------------------------------------------------------
template <int MODE>
__global__ __launch_bounds__(256, 2)
void gemm_mma(GP p0, GP p1)
{
    const GP p = (blockIdx.z == 0) ? p0 : p1;
    extern __shared__ float sm[];
    const uint32_t sb = smem_u32(sm);
    const int tid  = threadIdx.x;
    const int w    = tid >> 5;
    const int lane = tid & 31;
    const int g    = lane >> 2;
    const int tig  = lane & 3;
    const int wm   = w >> 2;
    const int wn   = w & 3;
    const int m0   = blockIdx.y * BM;
    const int n0   = blockIdx.x * BN;
    const int nk   = p.nk;

    float acc[4][4][4];
#pragma unroll
    for (int mt = 0; mt < 4; ++mt)
#pragma unroll
        for (int nt = 0; nt < 4; ++nt)
#pragma unroll
            for (int c = 0; c < 4; ++c) acc[mt][nt][c] = 0.0f;

    auto load_stage = [&](int kt, int s) {
        const int kb = kt * BK;
        const uint32_t base = sb + (uint32_t)(s * STAGE_F) * 4u;
#pragma unroll
        for (int i = 0; i < 4; ++i) {
            int idx = tid + 256 * i;
            int r = idx >> 3, q = idx & 7;
            cp16(base + (uint32_t)(r * PROW + q * 4) * 4u,
                 p.A + (size_t)(m0 + r) * p.lda + kb + q * 4);
        }
#pragma unroll
        for (int i = 0; i < 4; ++i) {
            int idx = tid + 256 * i;
            int r = idx >> 3, q = idx & 7;
            cp16(base + (uint32_t)(BM * PROW + r * PROW + q * 4) * 4u,
                 p.W + (size_t)(n0 + r) * p.ldw + p.kw0 + kb + q * 4);
        }
        cp_commit();
    };

    load_stage(0, 0);
    load_stage(1, 1);

#pragma unroll 1
    for (int kt = 0; kt < nk; ++kt) {
        if (kt + 1 < nk) cp_wait<1>(); else cp_wait<0>();
        __syncthreads();
        if (kt + 2 < nk) load_stage(kt + 2, (kt + 2) % NSTG);

        const float* As = sm + (kt % NSTG) * STAGE_F;
        const float* Bs = As + BM * PROW;
#pragma unroll
        for (int ks = 0; ks < 4; ++ks) {
            const int k0 = ks * 8;
            uint32_t a[4][4];
#pragma unroll
            for (int mt = 0; mt < 4; ++mt) {
                const float* ap = As + (wm * 64 + mt * 16 + g) * PROW + k0 + tig;
                a[mt][0] = __float_as_uint(ap[0]);
                a[mt][1] = __float_as_uint(ap[8 * PROW]);
                a[mt][2] = __float_as_uint(ap[4]);
                a[mt][3] = __float_as_uint(ap[8 * PROW + 4]);
            }
            uint32_t b[4][2];
#pragma unroll
            for (int nt = 0; nt < 4; ++nt) {
                const float* bp = Bs + (wn * 32 + nt * 8 + g) * PROW + k0 + tig;
                b[nt][0] = __float_as_uint(bp[0]);
                b[nt][1] = __float_as_uint(bp[4]);
            }
#pragma unroll
            for (int mt = 0; mt < 4; ++mt)
#pragma unroll
                for (int nt = 0; nt < 4; ++nt)
                    mma_tf32(acc[mt][nt][0], acc[mt][nt][1], acc[mt][nt][2], acc[mt][nt][3],
                             a[mt][0], a[mt][1], a[mt][2], a[mt][3],
                             b[nt][0], b[nt][1]);
        }
    }
    __syncthreads();

    // ---- stage accs through smem, then coalesced fused sweep ----
    float* stg = sm;                   // 128*132 floats < stage area
#pragma unroll
    for (int mt = 0; mt < 4; ++mt) {
#pragma unroll
        for (int nt = 0; nt < 4; ++nt) {
            const int m = wm * 64 + mt * 16 + g;
            const int n = wn * 32 + nt * 8 + tig * 2;
            stg[m * STGP + n]           = acc[mt][nt][0];
            stg[m * STGP + n + 1]       = acc[mt][nt][1];
            stg[(m + 8) * STGP + n]     = acc[mt][nt][2];
            stg[(m + 8) * STGP + n + 1] = acc[mt][nt][3];
        }
    }
    __syncthreads();

    for (int e = tid; e < BM * BN; e += 256) {
        const int mm = e >> 7;
        const int nc = e & 127;
        const size_t m = (size_t)(m0 + mm);
        const int n = n0 + nc;
        const float d = stg[mm * STGP + nc];
        if (MODE == 0) {
            p.C[m * p.ldc + n] = d + p.bias[n];
        } else if (MODE == 1) {
            float pre = d + (p.Xp ? p.Xp[m * NPROJ + n] : p.bias[n]);
            float gg = 1.0f / (1.0f + expf(-pre));
            if (n < 512) p.RH[m * p.ldh + n] = gg * p.Hin[m * p.ldh + n];
            else         p.Zg[m * 512 + n - 512] = gg;
        } else {
            float pre = d + (p.Xp ? p.Xp[m * NPROJ + 1024 + n] : p.bias[n]);
            float cn = tanhf(pre);
            float z  = p.Zg[m * 512 + n];
            float h  = p.Hin[m * p.ldh + n];
            float hn = h + z * (cn - h);
            p.D1[m * p.ld1 + n] = hn;
            if (p.D2) p.D2[m * p.ld2 + n] = hn;
            if (p.D3) p.D3[m * p.ld3 + n] = hn;
        }
    }
}

// ---------------------------------------------------------------------------
extern "C" void kernel_launch(void* const* d_in, const int* in_sizes, int n_in,
                              void* d_out, int out_size) {
    const float* x   = (const float*)d_in[0];
    const float* x0  = (const float*)d_in[1];
    const float* Wg0 = (const float*)d_in[2];
    const float* bg0 = (const float*)d_in[3];
    const float* Wc0 = (const float*)d_in[4];
    const float* bc0 = (const float*)d_in[5];
    const float* Wg1 = (const float*)d_in[6];
    const float* bg1 = (const float*)d_in[7];
    const float* Wc1 = (const float*)d_in[8];
    const float* bc1 = (const float*)d_in[9];
    float* out = (float*)d_out;
    (void)in_sizes; (void)n_in; (void)out_size;

    float *Xt, *Xp, *H0, *RH0, *Z0, *Z1, *catB, *rcatB;
    cudaGetSymbolAddress((void**)&Xt,   g_Xt);
    cudaGetSymbolAddress((void**)&Xp,   g_Xp);
    cudaGetSymbolAddress((void**)&H0,   g_H0);
    cudaGetSymbolAddress((void**)&RH0,  g_RH0);
    cudaGetSymbolAddress((void**)&Z0,   g_Z0);
    cudaGetSymbolAddress((void**)&Z1,   g_Z1);
    cudaGetSymbolAddress((void**)&catB,  g_cat);    // whole symbol, then offset
    cudaGetSymbolAddress((void**)&rcatB, g_rcat);
    const size_t PAR = (size_t)M_TOK * 1024;
    float* cat[2]  = {catB,  catB  + PAR};
    float* rcat[2] = {rcatB, rcatB + PAR};

    cudaFuncSetAttribute(gemm_mma<0>, cudaFuncAttributeMaxDynamicSharedMemorySize, SMEM_BYTES);
    cudaFuncSetAttribute(gemm_mma<1>, cudaFuncAttributeMaxDynamicSharedMemorySize, SMEM_BYTES);
    cudaFuncSetAttribute(gemm_mma<2>, cudaFuncAttributeMaxDynamicSharedMemorySize, SMEM_BYTES);

    GP z{};   // zeroed template

    // Phase A
    transpose_x<<<BATCH * T_STEPS, 256>>>(x, Xt);

    // Phase B: layer-0 x-side preacts (K=512)
    {
        GP pg = z; pg.A = Xt; pg.lda = 512; pg.W = Wg0; pg.ldw = 1024; pg.kw0 = 0;
        pg.nk = 16; pg.bias = bg0; pg.C = Xp; pg.ldc = NPROJ;
        gemm_mma<0><<<dim3(8, M_ALL / BM, 1), 256, SMEM_BYTES>>>(pg, pg);
        GP pc = z; pc.A = Xt; pc.lda = 512; pc.W = Wc0; pc.ldw = 1024; pc.kw0 = 0;
        pc.nk = 16; pc.bias = bc0; pc.C = Xp + 1024; pc.ldc = NPROJ;
        gemm_mma<0><<<dim3(4, M_ALL / BM, 1), 256, SMEM_BYTES>>>(pc, pc);
    }

    // init states
    zero_kern<<<(M_TOK * 512) / 256, 256>>>(H0, M_TOK * 512);
    zero_kern<<<(2 * M_TOK * 1024) / 256, 256>>>(catB, 2 * M_TOK * 1024);

    const size_t stepP = (size_t)M_TOK * NPROJ;

    // Pipelined recurrence: slot s runs L0 step t=s (s<16) and L1 step t=s-1 (s>=1)
    for (int s = 0; s <= T_STEPS; ++s) {
        const bool l0 = (s < T_STEPS);
        const bool l1 = (s >= 1);
        const int  p  = s & 1;            // L0 write parity
        const int  p2 = (s - 1) & 1;      // L1 read parity

        GP g0 = z, g1 = z, c0 = z, c1 = z;
        if (l0) {
            const float* Xpt = Xp + (size_t)s * stepP;
            g0.A = H0; g0.lda = 512; g0.W = Wg0; g0.ldw = 1024; g0.kw0 = 512; g0.nk = 16;
            g0.Xp = Xpt; g0.Hin = H0; g0.ldh = 512; g0.RH = RH0; g0.Zg = Z0;
            c0.A = RH0; c0.lda = 512; c0.W = Wc0; c0.ldw = 1024; c0.kw0 = 512; c0.nk = 16;
            c0.Xp = Xpt; c0.Hin = H0; c0.ldh = 512; c0.Zg = Z0;
            c0.D1 = H0; c0.ld1 = 512;
            c0.D2 = cat[p];  c0.ld2 = 1024;     // Y_t -> concat left
            c0.D3 = rcat[p]; c0.ld3 = 1024;
        }
        if (l1) {
            g1.A = cat[p2]; g1.lda = 1024; g1.W = Wg1; g1.ldw = 1024; g1.kw0 = 0; g1.nk = 32;
            g1.bias = bg1; g1.Xp = nullptr;
            g1.Hin = cat[p2] + 512; g1.ldh = 1024;
            g1.RH = rcat[p2] + 512; g1.Zg = Z1;
            c1.A = rcat[p2]; c1.lda = 1024; c1.W = Wc1; c1.ldw = 1024; c1.kw0 = 0; c1.nk = 32;
            c1.bias = bc1; c1.Xp = nullptr;
            c1.Hin = cat[p2] + 512; c1.ldh = 1024; c1.Zg = Z1;
            c1.D1 = cat[0] + 512; c1.ld1 = 1024;  // h1 -> both parities' right half
            c1.D2 = cat[1] + 512; c1.ld2 = 1024;
        }

        if (l0 && l1) {
            gemm_mma<1><<<dim3(8, M_TOK / BM, 2), 256, SMEM_BYTES>>>(g0, g1);
            gemm_mma<2><<<dim3(4, M_TOK / BM, 2), 256, SMEM_BYTES>>>(c0, c1);
        } else if (l0) {
            gemm_mma<1><<<dim3(8, M_TOK / BM, 1), 256, SMEM_BYTES>>>(g0, g0);
            gemm_mma<2><<<dim3(4, M_TOK / BM, 1), 256, SMEM_BYTES>>>(c0, c0);
        } else {
            gemm_mma<1><<<dim3(8, M_TOK / BM, 1), 256, SMEM_BYTES>>>(g1, g1);
            gemm_mma<2><<<dim3(4, M_TOK / BM, 1), 256, SMEM_BYTES>>>(c1, c1);
        }
    }

    // Output: h1 final lives in cat[0] right half (stride 1024)
    finalize_k<<<BATCH, 256>>>(cat[0] + 512, 1024, x0, out);
}

// round 8
// speedup vs baseline: 2.4180x; 1.0569x over previous
#include <cuda_runtime.h>
#include <math.h>
#include <stdint.h>

// ===========================================================================
// ConvGRU, mma.sync tf32 tensor cores (plain sm_100 target; tcgen05 unavailable).
// R8 = R7 + ldmatrix fragment loading (24 LDS.32 -> 6 LDSM.x4 per warp/kstep)
//      + zero_kern launches moved first so ncu -s5 lands on a GEMM.
//
//   zeros; A: transpose x -> token-major Xt
//   B: batch GEMM layer-0 x-side preacts Xp (K=512)            [MODE 0]
//   slots s=0..16:  gates [MODE 1] -> candidate [MODE 2], dual-z:
//        z=0: L0 step t=s   (K=512, Xp precomputed)
//        z=1: L1 step t=s-1 (K=1024, A = [Y_t | h1] / [Y_t | r*h1])
//   F: out = transpose(h1_last) + x0
// ===========================================================================

#define T_STEPS 16
#define BATCH   128
#define HID     512
#define SP      36
#define M_TOK   (BATCH * SP)          // 4608
#define M_ALL   (T_STEPS * M_TOK)     // 73728
#define NPROJ   1536

#define BM 128
#define BN 128
#define BK 32
#define PROW 36                       // smem row pitch (floats)
#define NSTG 3
#define STAGE_F ((BM + BN) * PROW)    // 9216 floats / stage
#define SMEM_BYTES (NSTG * STAGE_F * 4)   // 110592 B
#define STGP 132                      // epilogue staging pitch

// ---- scratch (static __device__ globals; no allocation) -------------------
__device__ float g_Xt [(size_t)M_ALL * 512];
__device__ float g_Xp [(size_t)M_ALL * NPROJ];
__device__ float g_H0 [(size_t)M_TOK * 512];
__device__ float g_RH0[(size_t)M_TOK * 512];
__device__ float g_Z0 [(size_t)M_TOK * 512];
__device__ float g_Z1 [(size_t)M_TOK * 512];
__device__ float g_cat [(size_t)2 * M_TOK * 1024];   // two parities of [Y_t | h1]
__device__ float g_rcat[(size_t)2 * M_TOK * 1024];   // two parities of [Y_t | r*h1]

// ---------------------------------------------------------------------------
struct GP {
    const float* A;  int lda;           // A is M x lda; K = 32*nk
    const float* W;  int ldw; int kw0;
    int nk;                             // K / 32
    const float* bias;
    float* C; int ldc;                  // MODE 0
    const float* Xp;                    // MODE 1/2 (L0); null -> use bias
    const float* Hin; int ldh;
    float* RH;                          // MODE 1 out (stride ldh)
    float* Zg;                          // MODE 1 out / MODE 2 in (stride 512)
    float* D1; int ld1;                 // MODE 2 dests (null-guarded D2/D3)
    float* D2; int ld2;
    float* D3; int ld3;
};

__device__ __forceinline__ uint32_t smem_u32(const void* p) {
    uint32_t a;
    asm("{ .reg .u64 t; cvta.to.shared.u64 t, %1; cvt.u32.u64 %0, t; }" : "=r"(a) : "l"(p));
    return a;
}
__device__ __forceinline__ void cp16(uint32_t dst, const void* src) {
    asm volatile("cp.async.cg.shared.global [%0], [%1], 16;" :: "r"(dst), "l"(src));
}
__device__ __forceinline__ void cp_commit() {
    asm volatile("cp.async.commit_group;" ::: "memory");
}
template <int N>
__device__ __forceinline__ void cp_wait() {
    asm volatile("cp.async.wait_group %0;" :: "n"(N) : "memory");
}
// ldmatrix x4: four 8x8 b16 matrices; on an fp32 tile (viewed as b16, one
// float = 2 adjacent b16) each lane reg = one fp32 element with the exact
// m16n8k8-tf32 fragment lane mapping.
__device__ __forceinline__ void ldsm4(uint32_t* r, uint32_t addr) {
    asm volatile("ldmatrix.sync.aligned.m8n8.x4.shared.b16 {%0,%1,%2,%3}, [%4];"
                 : "=r"(r[0]), "=r"(r[1]), "=r"(r[2]), "=r"(r[3]) : "r"(addr));
}
__device__ __forceinline__ void mma_tf32(float& d0, float& d1, float& d2, float& d3,
                                         uint32_t a0, uint32_t a1, uint32_t a2, uint32_t a3,
                                         uint32_t b0, uint32_t b1) {
    asm volatile(
        "mma.sync.aligned.m16n8k8.row.col.f32.tf32.tf32.f32 "
        "{%0,%1,%2,%3}, {%4,%5,%6,%7}, {%8,%9}, {%0,%1,%2,%3};"
        : "+f"(d0), "+f"(d1), "+f"(d2), "+f"(d3)
        : "r"(a0), "r"(a1), "r"(a2), "r"(a3), "r"(b0), "r"(b1));
}

// ---------------------------------------------------------------------------
__global__ void zero_kern(float* __restrict__ p, int n) {
    int i = blockIdx.x * blockDim.x + threadIdx.x;
    if (i < n) p[i] = 0.0f;
}

// transpose x[b][t][c][s] -> Xt[(t*4608 + b*36 + s)*512 + c]
__global__ void transpose_x(const float* __restrict__ x, float* __restrict__ Xt) {
    int bt = blockIdx.x;
    int b = bt / T_STEPS, t = bt % T_STEPS;
    const float* src = x + (size_t)bt * (512 * SP);
    float* dst = Xt + ((size_t)t * M_TOK + (size_t)b * SP) * 512;
    __shared__ float sm[256 * 37];
    for (int ch = 0; ch < 2; ++ch) {
        __syncthreads();
        const float* s2 = src + (size_t)ch * 256 * SP;
        for (int i = threadIdx.x; i < 256 * SP; i += 256) {
            int c = i / SP, s = i - c * SP;
            sm[c * 37 + s] = s2[i];
        }
        __syncthreads();
        for (int o = threadIdx.x; o < SP * 256; o += 256) {
            int s = o >> 8, c = o & 255;
            dst[(size_t)s * 512 + ch * 256 + c] = sm[c * 37 + s];
        }
    }
}

// out[b][n][s] = h1[(b*36+s)*ldh + n] + x0[b][n][s]
__global__ void finalize_k(const float* __restrict__ H, int ldh,
                           const float* __restrict__ x0, float* __restrict__ out) {
    int b = blockIdx.x;
    __shared__ float sm[SP * 261];
    for (int ch = 0; ch < 2; ++ch) {
        __syncthreads();
        for (int i = threadIdx.x; i < SP * 256; i += 256) {
            int s = i >> 8, c = i & 255;
            sm[s * 261 + c] = H[(size_t)(b * SP + s) * ldh + ch * 256 + c];
        }
        __syncthreads();
        for (int o = threadIdx.x; o < 256 * SP; o += 256) {
            int n = o / SP, s = o - n * SP;
            size_t oi = ((size_t)b * HID + ch * 256 + n) * SP + s;
            out[oi] = sm[s * 261 + n] + x0[oi];
        }
    }
}

// ---------------------------------------------------------------------------
// GEMM: D[m][n] = sum_{k<32*nk} A[m][k] * W[n][kw0 + k]   (tf32 mma, fp32 acc)
// MODE 0: C[m*ldc+n] = D + bias[n]
// MODE 1: g = sigmoid(D + (Xp ? Xp[m*1536+n] : bias[n]));
//         n<512: RH[m*ldh+n] = g*Hin[m*ldh+n];  else Zg[m*512+n-512] = g
// MODE 2: nn = tanh(D + (Xp ? Xp[m*1536+1024+n] : bias[n]));
//         h' = h + z*(nn-h) -> D1 (+D2,+D3)
// Dual-z: blockIdx.z selects p0/p1.
// ---------------------------------------------------------------------------
template <int MODE>
__global__ __launch_bounds__(256, 2)
void gemm_mma(GP p0, GP p1)
{
    const GP p = (blockIdx.z == 0) ? p0 : p1;
    extern __shared__ float sm[];
    const uint32_t sb = smem_u32(sm);
    const int tid  = threadIdx.x;
    const int w    = tid >> 5;
    const int lane = tid & 31;
    const int g    = lane >> 2;
    const int tig  = lane & 3;
    const int wm   = w >> 2;
    const int wn   = w & 3;
    const int m0   = blockIdx.y * BM;
    const int n0   = blockIdx.x * BN;
    const int nk   = p.nk;

    // per-lane ldmatrix row/col selectors
    const int arow = lane & 15;               // A: rows 0-15 of the 16-row tile
    const int asel = (lane >> 4) << 2;        //    cols k0+0 / k0+4
    const int brow = (lane & 7) + ((lane >> 4) << 3);   // B: nt-pair rows
    const int bsel = ((lane >> 3) & 1) << 2;  //    cols k0+0 / k0+4

    float acc[4][4][4];
#pragma unroll
    for (int mt = 0; mt < 4; ++mt)
#pragma unroll
        for (int nt = 0; nt < 4; ++nt)
#pragma unroll
            for (int c = 0; c < 4; ++c) acc[mt][nt][c] = 0.0f;

    auto load_stage = [&](int kt, int s) {
        const int kb = kt * BK;
        const uint32_t base = sb + (uint32_t)(s * STAGE_F) * 4u;
#pragma unroll
        for (int i = 0; i < 4; ++i) {
            int idx = tid + 256 * i;
            int r = idx >> 3, q = idx & 7;
            cp16(base + (uint32_t)(r * PROW + q * 4) * 4u,
                 p.A + (size_t)(m0 + r) * p.lda + kb + q * 4);
        }
#pragma unroll
        for (int i = 0; i < 4; ++i) {
            int idx = tid + 256 * i;
            int r = idx >> 3, q = idx & 7;
            cp16(base + (uint32_t)(BM * PROW + r * PROW + q * 4) * 4u,
                 p.W + (size_t)(n0 + r) * p.ldw + p.kw0 + kb + q * 4);
        }
        cp_commit();
    };

    load_stage(0, 0);
    load_stage(1, 1);

#pragma unroll 1
    for (int kt = 0; kt < nk; ++kt) {
        if (kt + 1 < nk) cp_wait<1>(); else cp_wait<0>();
        __syncthreads();
        if (kt + 2 < nk) load_stage(kt + 2, (kt + 2) % NSTG);

        const uint32_t As_u = sb + (uint32_t)((kt % NSTG) * STAGE_F) * 4u;
        const uint32_t Bs_u = As_u + (uint32_t)(BM * PROW) * 4u;

#pragma unroll
        for (int ks = 0; ks < 4; ++ks) {
            const int k0 = ks * 8;
            uint32_t a[4][4];
#pragma unroll
            for (int mt = 0; mt < 4; ++mt)
                ldsm4(a[mt], As_u +
                      (uint32_t)((wm * 64 + mt * 16 + arow) * PROW + k0 + asel) * 4u);
            uint32_t bb[2][4];
#pragma unroll
            for (int np = 0; np < 2; ++np)
                ldsm4(bb[np], Bs_u +
                      (uint32_t)((wn * 32 + np * 16 + brow) * PROW + k0 + bsel) * 4u);
#pragma unroll
            for (int mt = 0; mt < 4; ++mt)
#pragma unroll
                for (int nt = 0; nt < 4; ++nt)
                    mma_tf32(acc[mt][nt][0], acc[mt][nt][1], acc[mt][nt][2], acc[mt][nt][3],
                             a[mt][0], a[mt][1], a[mt][2], a[mt][3],
                             bb[nt >> 1][(nt & 1) * 2], bb[nt >> 1][(nt & 1) * 2 + 1]);
        }
    }
    __syncthreads();

    // ---- stage accs through smem, then coalesced fused sweep ----
    float* stg = sm;                   // 128*132 floats < stage area
#pragma unroll
    for (int mt = 0; mt < 4; ++mt) {
#pragma unroll
        for (int nt = 0; nt < 4; ++nt) {
            const int m = wm * 64 + mt * 16 + g;
            const int n = wn * 32 + nt * 8 + tig * 2;
            stg[m * STGP + n]           = acc[mt][nt][0];
            stg[m * STGP + n + 1]       = acc[mt][nt][1];
            stg[(m + 8) * STGP + n]     = acc[mt][nt][2];
            stg[(m + 8) * STGP + n + 1] = acc[mt][nt][3];
        }
    }
    __syncthreads();

    for (int e = tid; e < BM * BN; e += 256) {
        const int mm = e >> 7;
        const int nc = e & 127;
        const size_t m = (size_t)(m0 + mm);
        const int n = n0 + nc;
        const float d = stg[mm * STGP + nc];
        if (MODE == 0) {
            p.C[m * p.ldc + n] = d + p.bias[n];
        } else if (MODE == 1) {
            float pre = d + (p.Xp ? p.Xp[m * NPROJ + n] : p.bias[n]);
            float gg = 1.0f / (1.0f + expf(-pre));
            if (n < 512) p.RH[m * p.ldh + n] = gg * p.Hin[m * p.ldh + n];
            else         p.Zg[m * 512 + n - 512] = gg;
        } else {
            float pre = d + (p.Xp ? p.Xp[m * NPROJ + 1024 + n] : p.bias[n]);
            float cn = tanhf(pre);
            float z  = p.Zg[m * 512 + n];
            float h  = p.Hin[m * p.ldh + n];
            float hn = h + z * (cn - h);
            p.D1[m * p.ld1 + n] = hn;
            if (p.D2) p.D2[m * p.ld2 + n] = hn;
            if (p.D3) p.D3[m * p.ld3 + n] = hn;
        }
    }
}

// ---------------------------------------------------------------------------
extern "C" void kernel_launch(void* const* d_in, const int* in_sizes, int n_in,
                              void* d_out, int out_size) {
    const float* x   = (const float*)d_in[0];
    const float* x0  = (const float*)d_in[1];
    const float* Wg0 = (const float*)d_in[2];
    const float* bg0 = (const float*)d_in[3];
    const float* Wc0 = (const float*)d_in[4];
    const float* bc0 = (const float*)d_in[5];
    const float* Wg1 = (const float*)d_in[6];
    const float* bg1 = (const float*)d_in[7];
    const float* Wc1 = (const float*)d_in[8];
    const float* bc1 = (const float*)d_in[9];
    float* out = (float*)d_out;
    (void)in_sizes; (void)n_in; (void)out_size;

    float *Xt, *Xp, *H0, *RH0, *Z0, *Z1, *catB, *rcatB;
    cudaGetSymbolAddress((void**)&Xt,   g_Xt);
    cudaGetSymbolAddress((void**)&Xp,   g_Xp);
    cudaGetSymbolAddress((void**)&H0,   g_H0);
    cudaGetSymbolAddress((void**)&RH0,  g_RH0);
    cudaGetSymbolAddress((void**)&Z0,   g_Z0);
    cudaGetSymbolAddress((void**)&Z1,   g_Z1);
    cudaGetSymbolAddress((void**)&catB,  g_cat);    // whole symbol, then offset
    cudaGetSymbolAddress((void**)&rcatB, g_rcat);
    const size_t PAR = (size_t)M_TOK * 1024;
    float* cat[2]  = {catB,  catB  + PAR};
    float* rcat[2] = {rcatB, rcatB + PAR};

    cudaFuncSetAttribute(gemm_mma<0>, cudaFuncAttributeMaxDynamicSharedMemorySize, SMEM_BYTES);
    cudaFuncSetAttribute(gemm_mma<1>, cudaFuncAttributeMaxDynamicSharedMemorySize, SMEM_BYTES);
    cudaFuncSetAttribute(gemm_mma<2>, cudaFuncAttributeMaxDynamicSharedMemorySize, SMEM_BYTES);

    GP z{};   // zeroed template

    // init states FIRST (also puts ncu -s5 -c1 onto a recurrence GEMM)
    zero_kern<<<(M_TOK * 512) / 256, 256>>>(H0, M_TOK * 512);
    zero_kern<<<(2 * M_TOK * 1024) / 256, 256>>>(catB, 2 * M_TOK * 1024);

    // Phase A
    transpose_x<<<BATCH * T_STEPS, 256>>>(x, Xt);

    // Phase B: layer-0 x-side preacts (K=512)
    {
        GP pg = z; pg.A = Xt; pg.lda = 512; pg.W = Wg0; pg.ldw = 1024; pg.kw0 = 0;
        pg.nk = 16; pg.bias = bg0; pg.C = Xp; pg.ldc = NPROJ;
        gemm_mma<0><<<dim3(8, M_ALL / BM, 1), 256, SMEM_BYTES>>>(pg, pg);
        GP pc = z; pc.A = Xt; pc.lda = 512; pc.W = Wc0; pc.ldw = 1024; pc.kw0 = 0;
        pc.nk = 16; pc.bias = bc0; pc.C = Xp + 1024; pc.ldc = NPROJ;
        gemm_mma<0><<<dim3(4, M_ALL / BM, 1), 256, SMEM_BYTES>>>(pc, pc);
    }

    const size_t stepP = (size_t)M_TOK * NPROJ;

    // Pipelined recurrence: slot s runs L0 step t=s (s<16) and L1 step t=s-1 (s>=1)
    for (int s = 0; s <= T_STEPS; ++s) {
        const bool l0 = (s < T_STEPS);
        const bool l1 = (s >= 1);
        const int  pp = s & 1;            // L0 write parity
        const int  p2 = (s - 1) & 1;      // L1 read parity

        GP g0 = z, g1 = z, c0 = z, c1 = z;
        if (l0) {
            const float* Xpt = Xp + (size_t)s * stepP;
            g0.A = H0; g0.lda = 512; g0.W = Wg0; g0.ldw = 1024; g0.kw0 = 512; g0.nk = 16;
            g0.Xp = Xpt; g0.Hin = H0; g0.ldh = 512; g0.RH = RH0; g0.Zg = Z0;
            c0.A = RH0; c0.lda = 512; c0.W = Wc0; c0.ldw = 1024; c0.kw0 = 512; c0.nk = 16;
            c0.Xp = Xpt; c0.Hin = H0; c0.ldh = 512; c0.Zg = Z0;
            c0.D1 = H0; c0.ld1 = 512;
            c0.D2 = cat[pp];  c0.ld2 = 1024;    // Y_t -> concat left
            c0.D3 = rcat[pp]; c0.ld3 = 1024;
        }
        if (l1) {
            g1.A = cat[p2]; g1.lda = 1024; g1.W = Wg1; g1.ldw = 1024; g1.kw0 = 0; g1.nk = 32;
            g1.bias = bg1; g1.Xp = nullptr;
            g1.Hin = cat[p2] + 512; g1.ldh = 1024;
            g1.RH = rcat[p2] + 512; g1.Zg = Z1;
            c1.A = rcat[p2]; c1.lda = 1024; c1.W = Wc1; c1.ldw = 1024; c1.kw0 = 0; c1.nk = 32;
            c1.bias = bc1; c1.Xp = nullptr;
            c1.Hin = cat[p2] + 512; c1.ldh = 1024; c1.Zg = Z1;
            c1.D1 = cat[0] + 512; c1.ld1 = 1024;  // h1 -> both parities' right half
            c1.D2 = cat[1] + 512; c1.ld2 = 1024;
        }

        if (l0 && l1) {
            gemm_mma<1><<<dim3(8, M_TOK / BM, 2), 256, SMEM_BYTES>>>(g0, g1);
            gemm_mma<2><<<dim3(4, M_TOK / BM, 2), 256, SMEM_BYTES>>>(c0, c1);
        } else if (l0) {
            gemm_mma<1><<<dim3(8, M_TOK / BM, 1), 256, SMEM_BYTES>>>(g0, g0);
            gemm_mma<2><<<dim3(4, M_TOK / BM, 1), 256, SMEM_BYTES>>>(c0, c0);
        } else {
            gemm_mma<1><<<dim3(8, M_TOK / BM, 1), 256, SMEM_BYTES>>>(g1, g1);
            gemm_mma<2><<<dim3(4, M_TOK / BM, 1), 256, SMEM_BYTES>>>(c1, c1);
        }
    }

    // Output: h1 final lives in cat[0] right half (stride 1024)
    finalize_k<<<BATCH, 256>>>(cat[0] + 512, 1024, x0, out);
}